// round 3
// baseline (speedup 1.0000x reference)
#include <cuda_runtime.h>
#include <cuda_bf16.h>

#define BB 8
#define CC 256
#define HH 64
#define WW 64
#define OO 256
#define KK2 9
#define PLANE (HH * WW)    // 4096
#define NS (KK2 * WW)      // 576 sample slots per row
#define NW4 (KK2 * OO / 4) // 576 float4 weight slots per c

typedef unsigned long long u64t;

__device__ __forceinline__ u64t fma2(u64t a, u64t b, u64t c) {
    u64t d;
    asm("fma.rn.f32x2 %0, %1, %2, %3;" : "=l"(d) : "l"(a), "l"(b), "l"(c));
    return d;
}
__device__ __forceinline__ u64t dup2(float v) {
    u64t d;
    asm("mov.b64 %0, {%1, %1};" : "=l"(d) : "f"(v));
    return d;
}
__device__ __forceinline__ void unpack2(u64t v, float& lo, float& hi) {
    asm("mov.b64 {%0, %1}, %2;" : "=f"(lo), "=f"(hi) : "l"(v));
}

// Pre-transposed weight: wT[c][k][o]  (c*2304 + k*256 + o)
__device__ float g_wT[CC * KK2 * OO];

__global__ void transpose_w_kernel(const float* __restrict__ w) {
    int n = blockIdx.x * blockDim.x + threadIdx.x;   // over O*C*K2 = 589824
    if (n >= OO * CC * KK2) return;
    int o = n / (CC * KK2);
    int r = n % (CC * KK2);
    int c = r / KK2;
    int k = r % KK2;
    g_wT[(c * KK2 + k) * OO + o] = w[n];
}

__global__ __launch_bounds__(256, 2)
void dcn_kernel(const float* __restrict__ x,
                const float* __restrict__ offset,
                float* __restrict__ out) {
    const int h   = blockIdx.x;          // output row
    const int b   = blockIdx.y;          // batch
    const int tid = threadIdx.x;
    const int to  = tid >> 4;            // 0..15 : o-subtile (16 o's each)
    const int tp  = tid & 15;            // 0..15 : p-subtile (4 px each)

    __shared__ int4   sidx[NS];          // bilinear tap indices (clamped)
    __shared__ float4 swgt[NS];          // bilinear tap weights (zeroed if OOB)
    __shared__ float  S[2][NS];          // double-buffered sampled values
    __shared__ float4 W4[2][NW4];        // double-buffered weights [k*64 + o/4]

    // ---- Precompute bilinear gather indices+weights, shared across all c ----
    for (int i = tid; i < NS; i += 256) {
        int k = i >> 6;                  // 0..8
        int p = i & 63;                  // 0..63
        int ky = k / 3, kx = k % 3;
        const float dy = offset[(((b * 2 * KK2 + 2 * k    ) * HH + h) * WW) + p];
        const float dx = offset[(((b * 2 * KK2 + 2 * k + 1) * HH + h) * WW) + p];
        float py = (float)(h - 1 + ky) + dy;
        float px = (float)(p - 1 + kx) + dx;
        float y0f = floorf(py), x0f = floorf(px);
        float fy = py - y0f,    fx = px - x0f;
        int iy0 = (int)y0f, ix0 = (int)x0f;
        int iy1 = iy0 + 1,  ix1 = ix0 + 1;
        bool vy0 = (iy0 >= 0) && (iy0 < HH);
        bool vy1 = (iy1 >= 0) && (iy1 < HH);
        bool vx0 = (ix0 >= 0) && (ix0 < WW);
        bool vx1 = (ix1 >= 0) && (ix1 < WW);
        float w00 = (1.f - fy) * (1.f - fx);
        float w01 = (1.f - fy) * fx;
        float w10 = fy * (1.f - fx);
        float w11 = fy * fx;
        int4   id;
        float4 wg;
        id.x = (vy0 && vx0) ? (iy0 * WW + ix0) : 0;  wg.x = (vy0 && vx0) ? w00 : 0.f;
        id.y = (vy0 && vx1) ? (iy0 * WW + ix1) : 0;  wg.y = (vy0 && vx1) ? w01 : 0.f;
        id.z = (vy1 && vx0) ? (iy1 * WW + ix0) : 0;  wg.z = (vy1 && vx0) ? w10 : 0.f;
        id.w = (vy1 && vx1) ? (iy1 * WW + ix1) : 0;  wg.w = (vy1 && vx1) ? w11 : 0.f;
        sidx[i] = id;
        swgt[i] = wg;
    }

    // 32 packed accumulators: pair lanes = (o, o+1); index [(i*2+pb)*4 + p]
    // covers o_local = i*4 + pb*2 + {0,1}, pixel p = tp*4 + p
    u64t acc2[32];
#pragma unroll
    for (int i = 0; i < 32; i++) acc2[i] = 0ull;

    const float*  xb  = x + (size_t)b * CC * PLANE;
    const float4* wT4 = (const float4*)g_wT;

    // Per-thread prefetch registers: up to 3 slots (tid<64 owns 3, else 2)
    float4 rW[3];
    float  rs[3][4];
    const bool has3 = (tid < NS - 512);   // tid < 64

    __syncthreads();   // sidx/swgt ready before first prefetch reads them

    // ---- Prefetch c = 0 (raw taps + weights) ----
    {
        const float4* wp = wT4;
        const float*  xp = xb;
#pragma unroll
        for (int j = 0; j < 3; j++) {
            int i = tid + j * 256;
            if (j < 2 || has3) {
                rW[j] = wp[i];
                int4 id = sidx[i];
                rs[j][0] = __ldg(xp + id.x);
                rs[j][1] = __ldg(xp + id.y);
                rs[j][2] = __ldg(xp + id.z);
                rs[j][3] = __ldg(xp + id.w);
            }
        }
    }

    int cur = 0;
    for (int c = 0; c < CC; c++) {
        // ---- Stage prefetched data into smem buffer 'cur' ----
#pragma unroll
        for (int j = 0; j < 3; j++) {
            int i = tid + j * 256;
            if (j < 2 || has3) {
                W4[cur][i] = rW[j];
                float4 wg = swgt[i];
                S[cur][i] = wg.x * rs[j][0] + wg.y * rs[j][1]
                          + wg.z * rs[j][2] + wg.w * rs[j][3];
            }
        }
        __syncthreads();

        // ---- Issue prefetch LDGs for c+1 (consumed next iteration) ----
        if (c + 1 < CC) {
            const float4* wp = wT4 + (c + 1) * NW4;
            const float*  xp = xb + (c + 1) * PLANE;
#pragma unroll
            for (int j = 0; j < 3; j++) {
                int i = tid + j * 256;
                if (j < 2 || has3) {
                    rW[j] = wp[i];
                    int4 id = sidx[i];
                    rs[j][0] = __ldg(xp + id.x);
                    rs[j][1] = __ldg(xp + id.y);
                    rs[j][2] = __ldg(xp + id.z);
                    rs[j][3] = __ldg(xp + id.w);
                }
            }
        }

        // ---- Rank-1 update with packed f32x2 FMA:
        //      9 taps x 32 FFMA2 per thread (pairs along o) ----
        const float4* S4 = (const float4*)S[cur];
        const u64t*   Wc = (const u64t*)W4[cur];   // [k*128 + o/2] pairs
#pragma unroll
        for (int k = 0; k < KK2; k++) {
            float4 s = S4[k * 16 + tp];
            u64t sd[4];
            sd[0] = dup2(s.x); sd[1] = dup2(s.y);
            sd[2] = dup2(s.z); sd[3] = dup2(s.w);
            const u64t* wr = Wc + k * 128 + to * 8;   // 8 o-pairs for this thread
#pragma unroll
            for (int i = 0; i < 4; i++) {
                u64t w0 = wr[i * 2 + 0];   // (w[4i],   w[4i+1])
                u64t w1 = wr[i * 2 + 1];   // (w[4i+2], w[4i+3])
#pragma unroll
                for (int p = 0; p < 4; p++) {
                    acc2[(i * 2 + 0) * 4 + p] = fma2(w0, sd[p], acc2[(i * 2 + 0) * 4 + p]);
                    acc2[(i * 2 + 1) * 4 + p] = fma2(w1, sd[p], acc2[(i * 2 + 1) * 4 + p]);
                }
            }
        }
        cur ^= 1;
    }

    // ---- Epilogue: unpack pairs; out[b][o][h][w], w = tp*4..tp*4+3 ----
#pragma unroll
    for (int i = 0; i < 4; i++) {
#pragma unroll
        for (int pb = 0; pb < 2; pb++) {
            float lo[4], hi[4];
#pragma unroll
            for (int p = 0; p < 4; p++)
                unpack2(acc2[(i * 2 + pb) * 4 + p], lo[p], hi[p]);
            int o0 = to * 16 + i * 4 + pb * 2;
            float* op0 = out + ((((size_t)b * OO + o0    ) * HH + h) * WW) + tp * 4;
            float* op1 = out + ((((size_t)b * OO + o0 + 1) * HH + h) * WW) + tp * 4;
            *(float4*)op0 = make_float4(lo[0], lo[1], lo[2], lo[3]);
            *(float4*)op1 = make_float4(hi[0], hi[1], hi[2], hi[3]);
        }
    }
}

extern "C" void kernel_launch(void* const* d_in, const int* in_sizes, int n_in,
                              void* d_out, int out_size) {
    const float* x      = (const float*)d_in[0];   // [8,256,64,64]
    const float* offset = (const float*)d_in[1];   // [8,18,64,64]
    const float* weight = (const float*)d_in[2];   // [256,256,3,3]
    float* out = (float*)d_out;                    // [8,256,64,64]

    int nw = OO * CC * KK2;
    transpose_w_kernel<<<(nw + 255) / 256, 256>>>(weight);

    dim3 grid(HH, BB);   // (h, b)
    dcn_kernel<<<grid, 256>>>(x, offset, out);
}

// round 5
// speedup vs baseline: 2.8409x; 2.8409x over previous
#include <cuda_runtime.h>
#include <cuda_fp16.h>
#include <cstdint>

#define BB 8
#define CC 256
#define HH 64
#define WW 64
#define OO 256
#define KK2 9
#define PLANE 4096
#define NROWS 4
#define NPIX 256          // N per CTA
#define NCH 144           // chunks: 16 c-groups (outer) x 9 taps (inner)
#define APITCH 48
#define BPITCH 48
#define A_BUF_BYTES (128 * APITCH)   // 6144
#define B_BUF_BYTES (256 * BPITCH)   // 12288

// smem layout (dynamic)
#define SM_IDX 0                     // ushort4[9*256] = 18432
#define SM_WGT 18432                 // float4 [9*256] = 36864 -> 55296
#define SM_A   55296                 // 2 * 6144  -> 67584
#define SM_B   67584                 // 2 * 12288 -> 92160
#define SMEM_TOTAL 92160

__device__ __forceinline__ uint32_t smem_u32(const void* p) {
    uint32_t a;
    asm("{ .reg .u64 t; cvta.to.shared.u64 t, %1; cvt.u32.u64 %0, t; }"
        : "=r"(a) : "l"(p));
    return a;
}

__device__ __forceinline__ void ldmx4(uint32_t* r, uint32_t addr) {
    asm volatile("ldmatrix.sync.aligned.m8n8.x4.shared.b16 {%0,%1,%2,%3}, [%4];"
                 : "=r"(r[0]), "=r"(r[1]), "=r"(r[2]), "=r"(r[3]) : "r"(addr));
}

__device__ __forceinline__ void mma16816(float* d, const uint32_t* a,
                                         uint32_t b0, uint32_t b1) {
    asm volatile(
        "mma.sync.aligned.m16n8k16.row.col.f32.f16.f16.f32 "
        "{%0,%1,%2,%3}, {%4,%5,%6,%7}, {%8,%9}, {%0,%1,%2,%3};"
        : "+f"(d[0]), "+f"(d[1]), "+f"(d[2]), "+f"(d[3])
        : "r"(a[0]), "r"(a[1]), "r"(a[2]), "r"(a[3]), "r"(b0), "r"(b1));
}

// Pre-packed fp16 weights, chunk-major: g_wh[q][o][j], q = cg*9 + k, j = c-local
__device__ __half g_wh[NCH * OO * 16];   // 1.18 MB

__global__ void prep_w(const float* __restrict__ w) {
    int n = blockIdx.x * blockDim.x + threadIdx.x;   // over 144*256*16
    if (n >= NCH * OO * 16) return;
    int j = n & 15;
    int o = (n >> 4) & 255;
    int q = n >> 12;
    int cg = q / 9;
    int k  = q - cg * 9;
    int c  = cg * 16 + j;
    g_wh[n] = __float2half(w[(o * CC + c) * KK2 + k]);
}

__global__ __launch_bounds__(256, 1)
void dcn_kernel(const float* __restrict__ x,
                const float* __restrict__ offset,
                float* __restrict__ out) {
    extern __shared__ char smem[];
    ushort4* sidx = (ushort4*)(smem + SM_IDX);   // [k*256 + p]
    float4*  swgt = (float4*) (smem + SM_WGT);

    const int tid = threadIdx.x;
    const int lid = tid & 31;
    const int wid = tid >> 5;
    const int wm  = wid >> 2;            // 0..1 : warp m (64 rows)
    const int wn  = wid & 3;             // 0..3 : warp n (64 px)
    const int b   = blockIdx.y;
    const int h0  = blockIdx.x * NROWS;
    const int mh  = blockIdx.z;          // o-half (0/1)

    // ---- precompute bilinear taps per (k, pixel) ----
    for (int i = tid; i < KK2 * NPIX; i += 256) {
        int k = i >> 8;
        int p = i & 255;
        int rl = p >> 6, wc = p & 63;
        int h = h0 + rl;
        int ky = k / 3, kx = k - ky * 3;
        float dy = offset[(((b * 2 * KK2 + 2 * k    ) * HH + h) * WW) + wc];
        float dx = offset[(((b * 2 * KK2 + 2 * k + 1) * HH + h) * WW) + wc];
        float py = (float)(h - 1 + ky) + dy;
        float px = (float)(wc - 1 + kx) + dx;
        float y0f = floorf(py), x0f = floorf(px);
        float fy = py - y0f, fx = px - x0f;
        int iy0 = (int)y0f, ix0 = (int)x0f;
        int iy1 = iy0 + 1,  ix1 = ix0 + 1;
        bool vy0 = (iy0 >= 0) && (iy0 < HH);
        bool vy1 = (iy1 >= 0) && (iy1 < HH);
        bool vx0 = (ix0 >= 0) && (ix0 < WW);
        bool vx1 = (ix1 >= 0) && (ix1 < WW);
        ushort4 id;
        id.x = (vy0 && vx0) ? (unsigned short)(iy0 * WW + ix0) : 0;
        id.y = (vy0 && vx1) ? (unsigned short)(iy0 * WW + ix1) : 0;
        id.z = (vy1 && vx0) ? (unsigned short)(iy1 * WW + ix0) : 0;
        id.w = (vy1 && vx1) ? (unsigned short)(iy1 * WW + ix1) : 0;
        float4 wg;
        wg.x = (vy0 && vx0) ? (1.f - fy) * (1.f - fx) : 0.f;
        wg.y = (vy0 && vx1) ? (1.f - fy) * fx : 0.f;
        wg.z = (vy1 && vx0) ? fy * (1.f - fx) : 0.f;
        wg.w = (vy1 && vx1) ? fy * fx : 0.f;
        sidx[i] = id;
        swgt[i] = wg;
    }
    __syncthreads();

    const uint32_t smA = smem_u32(smem + SM_A);
    const uint32_t smB = smem_u32(smem + SM_B);

    // ldmatrix per-thread address offsets (within a buffer)
    const int r   = lid & 7;
    const int sec = lid >> 3;
    // A frag order: r0:(m+r,k0-7) r1:(m+8+r,k0-7) r2:(m+r,k8-15) r3:(m+8+r,k8-15)
    const uint32_t aoff = (uint32_t)(wm * 64 + r + 8 * (sec & 1)) * APITCH
                        + (uint32_t)(sec >> 1) * 16;
    // B frag order: r0:(n+r,k0-7) r1:(n+r,k8-15) r2:(n+8+r,k0-7) r3:(n+8+r,k8-15)
    const uint32_t boff = (uint32_t)(wn * 64 + r + 8 * (sec >> 1)) * BPITCH
                        + (uint32_t)(sec & 1) * 16;

    const float* xb = x + (size_t)b * CC * PLANE;
    const char*  wsrc = (const char*)g_wh + (size_t)mh * 4096;  // m-half offset
    const int arow = tid >> 1, ahalf = tid & 1;

    float acc[4][8][4];
#pragma unroll
    for (int i = 0; i < 4; i++)
#pragma unroll
        for (int j = 0; j < 8; j++)
#pragma unroll
            for (int t = 0; t < 4; t++) acc[i][j][t] = 0.f;

    uint32_t sbuf[8];    // 16 fp16 samples (this thread's pixel, 16 channels)
    uint4    areg;       // 16B of A tile for this thread

    // ---- prologue: prefetch chunk 0 ----
    {
        ushort4 id = sidx[tid];          // k=0
        float4  wg = swgt[tid];
        const float* xp = xb;            // cg=0
#pragma unroll
        for (int jj = 0; jj < 8; jj++) {
            float s0 = wg.x * __ldg(xp + id.x) + wg.y * __ldg(xp + id.y)
                     + wg.z * __ldg(xp + id.z) + wg.w * __ldg(xp + id.w);
            xp += PLANE;
            float s1 = wg.x * __ldg(xp + id.x) + wg.y * __ldg(xp + id.y)
                     + wg.z * __ldg(xp + id.z) + wg.w * __ldg(xp + id.w);
            xp += PLANE;
            __half2 hh = __floats2half2_rn(s0, s1);
            sbuf[jj] = *(uint32_t*)&hh;
        }
        areg = *(const uint4*)(wsrc + arow * 32 + ahalf * 16);
    }

    int k_nxt = 1, cg_nxt = 0;   // chunk coordinates for q+1

    for (int q = 0; q < NCH; q++) {
        const int buf = q & 1;
        const uint32_t abase = smA + buf * A_BUF_BYTES;
        const uint32_t bbase = smB + buf * B_BUF_BYTES;

        // ---- stage prefetched A/B into smem ----
        {
            char* ad = smem + SM_A + buf * A_BUF_BYTES + arow * APITCH + ahalf * 16;
            *(uint4*)ad = areg;
            char* bd = smem + SM_B + buf * B_BUF_BYTES + tid * BPITCH;
            *(uint4*)(bd)      = *(uint4*)&sbuf[0];
            *(uint4*)(bd + 16) = *(uint4*)&sbuf[4];
        }
        __syncthreads();

        // ---- prefetch chunk q+1 (overlaps with MMA below) ----
        if (q + 1 < NCH) {
            ushort4 id = sidx[k_nxt * 256 + tid];
            float4  wg = swgt[k_nxt * 256 + tid];
            const float* xp = xb + cg_nxt * (16 * PLANE);
#pragma unroll
            for (int jj = 0; jj < 8; jj++) {
                float s0 = wg.x * __ldg(xp + id.x) + wg.y * __ldg(xp + id.y)
                         + wg.z * __ldg(xp + id.z) + wg.w * __ldg(xp + id.w);
                xp += PLANE;
                float s1 = wg.x * __ldg(xp + id.x) + wg.y * __ldg(xp + id.y)
                         + wg.z * __ldg(xp + id.z) + wg.w * __ldg(xp + id.w);
                xp += PLANE;
                __half2 hh = __floats2half2_rn(s0, s1);
                sbuf[jj] = *(uint32_t*)&hh;
            }
            areg = *(const uint4*)(wsrc + (size_t)(q + 1) * 8192
                                   + arow * 32 + ahalf * 16);
            if (++k_nxt == KK2) { k_nxt = 0; cg_nxt++; }
        }

        // ---- ldmatrix + 32 MMAs on buffer 'buf' ----
        uint32_t af[4][4], bf[4][4];
#pragma unroll
        for (int mt = 0; mt < 4; mt++)
            ldmx4(af[mt], abase + aoff + mt * 16 * APITCH);
#pragma unroll
        for (int ng = 0; ng < 4; ng++)
            ldmx4(bf[ng], bbase + boff + ng * 16 * BPITCH);
#pragma unroll
        for (int mt = 0; mt < 4; mt++)
#pragma unroll
            for (int ng = 0; ng < 4; ng++) {
                mma16816(acc[mt][2 * ng],     af[mt], bf[ng][0], bf[ng][1]);
                mma16816(acc[mt][2 * ng + 1], af[mt], bf[ng][2], bf[ng][3]);
            }
    }

    // ---- epilogue ----
    const int ml = lid >> 2;         // 0..7
    const int nl = (lid & 3) * 2;    // 0,2,4,6
#pragma unroll
    for (int mt = 0; mt < 4; mt++) {
#pragma unroll
        for (int nt = 0; nt < 8; nt++) {
            int o = mh * 128 + wm * 64 + mt * 16 + ml;
            int n = wn * 64 + nt * 8 + nl;
            int h = h0 + (n >> 6);
            int wc = n & 63;
            float* op = out + (((size_t)b * OO + o) * HH + h) * WW + wc;
            *(float2*)op = make_float2(acc[mt][nt][0], acc[mt][nt][1]);
            float* op2 = op + (size_t)8 * HH * WW;    // o + 8
            *(float2*)op2 = make_float2(acc[mt][nt][2], acc[mt][nt][3]);
        }
    }
}

extern "C" void kernel_launch(void* const* d_in, const int* in_sizes, int n_in,
                              void* d_out, int out_size) {
    const float* x      = (const float*)d_in[0];   // [8,256,64,64]
    const float* offset = (const float*)d_in[1];   // [8,18,64,64]
    const float* weight = (const float*)d_in[2];   // [256,256,3,3]
    float* out = (float*)d_out;                    // [8,256,64,64]

    cudaFuncSetAttribute(dcn_kernel,
                         cudaFuncAttributeMaxDynamicSharedMemorySize, SMEM_TOTAL);

    int nprep = NCH * OO * 16;
    prep_w<<<(nprep + 255) / 256, 256>>>(weight);

    dim3 grid(HH / NROWS, BB, 2);    // (16 rowgroups, 8 batches, 2 o-halves)
    dcn_kernel<<<grid, 256, SMEM_TOTAL>>>(x, offset, out);
}